// round 4
// baseline (speedup 1.0000x reference)
#include <cuda_runtime.h>
#include <cuda_bf16.h>
#include <cstddef>

// NetAE batch-1 forward: HBM-bound GEMV chain (~596MB fp32 weights/call).
// Split-K GEMV; previous stage's reduction+bias+relu fused into consumer's
// x-staging prologue. Round 4: float4-vectorized prologues, explicit 4-row
// load batching (deep MLP), __ldcs streaming weight reads.

#define D_H    2048
#define D_A    256
#define N_EXP  16
#define D_OUT  512

__device__ float g_pA[128 * 2048];
__device__ float g_pB[128 * 2048];
__device__ float g_pC[16 * 32 * 2048];
__device__ float g_pD[16 * 128 * 256];
__device__ float g_pE[16 * 32 * 2048];
__device__ float g_pF[128 * 2048];
__device__ float g_pG[256 * 512];
__device__ float g_ekq[16];

__device__ __forceinline__ float4 f4add(float4 a, float4 b) {
    return make_float4(a.x + b.x, a.y + b.y, a.z + b.z, a.w + b.w);
}

// ---------------------------------------------------------------------------
// Split-K GEMV with fused, float4-vectorized x-staging.
//   MODE 0: x[r] = xsrc[i0+r]
//   MODE 1: x[r] = [relu](biasx[bb*NPREV+i0+r] + sum_{s<SPREV} xsrc[(bb*SPREV+s)*NPREV+i0+r])
//   MODE 2: x[r] = sum_{s<SPREV} xsrc[s*NPREV+i0+r] + sum_n ekq[n]*bv[n*NPREV+i0+r]
// Block: RPS rows x (BLK/GRP)*4 cols; GRP row-groups each write their own
// partial slice: partOut[((b*S+slice)*GRP+g)*N + j] (float4, no atomics).
// ---------------------------------------------------------------------------
template<int BLK, int RPS, int N, int GRP, int MODE, int SPREV, int NPREV,
         bool RELU_X, bool SCALE_OUT, bool PREV_PER_B>
__global__ __launch_bounds__(BLK)
void gemv_k(const float* __restrict__ W,
            const float* __restrict__ xsrc,
            const float* __restrict__ biasx,
            const float* __restrict__ bv,
            const float* __restrict__ ekq,
            float* __restrict__ partOut)
{
    __shared__ float sx[RPS];
    const int tid   = threadIdx.x;
    const int slice = blockIdx.y;
    const int b     = blockIdx.z;
    const int S     = gridDim.y;
    const int i0    = slice * RPS;
    const int K     = S * RPS;

    if constexpr (MODE == 0) {
        for (int r = tid; r < RPS; r += BLK) sx[r] = xsrc[i0 + r];
        __syncthreads();
    } else {
        constexpr int NQ = RPS / 4;        // float4 quads per slice row
        constexpr int CH = BLK / NQ;       // threads (chunks) per quad
        __shared__ float4 sxp4[BLK];
        const int q = tid % NQ;
        const int c = tid / NQ;
        const int bb = (PREV_PER_B && MODE == 1) ? b : 0;
        const float4* p = reinterpret_cast<const float4*>(
            xsrc + ((size_t)bb * SPREV) * NPREV + i0);
        float4 v = make_float4(0.f, 0.f, 0.f, 0.f);
        #pragma unroll
        for (int s = c; s < SPREV; s += CH)
            v = f4add(v, p[(size_t)s * (NPREV / 4) + q]);
        sxp4[tid] = v;
        __syncthreads();
        if (tid < NQ) {
            float4 v2;
            if constexpr (MODE == 1) {
                v2 = reinterpret_cast<const float4*>(
                         biasx + (size_t)bb * NPREV + i0)[tid];
            } else {
                v2 = make_float4(0.f, 0.f, 0.f, 0.f);
                #pragma unroll
                for (int n = 0; n < N_EXP; n++) {
                    const float4 bq = reinterpret_cast<const float4*>(
                        bv + (size_t)n * NPREV + i0)[tid];
                    const float e = ekq[n];
                    v2.x += e * bq.x; v2.y += e * bq.y;
                    v2.z += e * bq.z; v2.w += e * bq.w;
                }
            }
            #pragma unroll
            for (int cc = 0; cc < CH; cc++) v2 = f4add(v2, sxp4[tid + cc * NQ]);
            if constexpr (RELU_X) {
                v2.x = fmaxf(v2.x, 0.f); v2.y = fmaxf(v2.y, 0.f);
                v2.z = fmaxf(v2.z, 0.f); v2.w = fmaxf(v2.w, 0.f);
            }
            reinterpret_cast<float4*>(sx)[tid] = v2;
        }
        __syncthreads();
    }

    constexpr int CT  = BLK / GRP;      // float4 cols per group
    constexpr int RPG = RPS / GRP;      // rows per group
    const int g  = tid / CT;
    const int j  = (blockIdx.x * CT + (tid % CT)) * 4;
    const int r0 = g * RPG;

    const float* Wp = W + (size_t)b * K * N + (size_t)(i0 + r0) * N + j;
    float4 acc = make_float4(0.f, 0.f, 0.f, 0.f);
    #pragma unroll
    for (int rr = 0; rr < RPG; rr += 4) {
        const float4 w0 = __ldcs(reinterpret_cast<const float4*>(Wp + (size_t)(rr + 0) * N));
        const float4 w1 = __ldcs(reinterpret_cast<const float4*>(Wp + (size_t)(rr + 1) * N));
        const float4 w2 = __ldcs(reinterpret_cast<const float4*>(Wp + (size_t)(rr + 2) * N));
        const float4 w3 = __ldcs(reinterpret_cast<const float4*>(Wp + (size_t)(rr + 3) * N));
        const float x0 = sx[r0 + rr + 0], x1 = sx[r0 + rr + 1];
        const float x2 = sx[r0 + rr + 2], x3 = sx[r0 + rr + 3];
        acc.x += x0 * w0.x; acc.y += x0 * w0.y; acc.z += x0 * w0.z; acc.w += x0 * w0.w;
        acc.x += x1 * w1.x; acc.y += x1 * w1.y; acc.z += x1 * w1.z; acc.w += x1 * w1.w;
        acc.x += x2 * w2.x; acc.y += x2 * w2.y; acc.z += x2 * w2.z; acc.w += x2 * w2.w;
        acc.x += x3 * w3.x; acc.y += x3 * w3.y; acc.z += x3 * w3.z; acc.w += x3 * w3.w;
    }
    if constexpr (SCALE_OUT) {
        const float sc = ekq[b];
        acc.x *= sc; acc.y *= sc; acc.z *= sc; acc.w *= sc;
    }
    *reinterpret_cast<float4*>(
        partOut + ((size_t)((b * S + slice) * GRP + g)) * N + j) = acc;
}

// expkq[n] = (b_k[n] + reduce_{s<128} pD[n]) . (W_q[t][t] + b_q[t])
// one block per expert, 256 threads = 64 quads x 4 slice-chunks (float4).
__global__ __launch_bounds__(256)
void fin_expkq(const float* __restrict__ part,
               const float* __restrict__ b_k,
               const float* __restrict__ W_q,
               const float* __restrict__ b_q,
               const int* __restrict__ task_id,
               float* __restrict__ expkq)
{
    __shared__ float4 red4[256];
    __shared__ float red[64];
    const int n = blockIdx.x;
    const int q = threadIdx.x % 64;
    const int c = threadIdx.x / 64;
    const int t = *task_id;
    const float4* p = reinterpret_cast<const float4*>(part + (size_t)n * 128 * D_A);
    float4 acc = make_float4(0.f, 0.f, 0.f, 0.f);
    #pragma unroll
    for (int s = c; s < 128; s += 4) acc = f4add(acc, p[(size_t)s * 64 + q]);
    red4[threadIdx.x] = acc;
    __syncthreads();
    if (threadIdx.x < 64) {
        float4 k = f4add(f4add(red4[q], red4[q + 64]),
                         f4add(red4[q + 128], red4[q + 192]));
        k = f4add(k, reinterpret_cast<const float4*>(b_k + n * D_A)[q]);
        const float4 wq = reinterpret_cast<const float4*>(
            W_q + ((size_t)t * 10 + t) * D_A)[q];
        const float4 bq = reinterpret_cast<const float4*>(b_q + t * D_A)[q];
        red[q] = k.x * (wq.x + bq.x) + k.y * (wq.y + bq.y)
               + k.z * (wq.z + bq.z) + k.w * (wq.w + bq.w);
    }
    __syncthreads();
    if (threadIdx.x < 32) {
        float v = red[threadIdx.x] + red[threadIdx.x + 32];
        #pragma unroll
        for (int off = 16; off; off >>= 1) v += __shfl_xor_sync(0xFFFFFFFFu, v, off);
        if (threadIdx.x == 0) expkq[n] = v;
    }
}

// out[j] = b_l[j] + reduce_{s<256} pG[s*512 + j]; 2 blocks x 256 thr (float4).
__global__ __launch_bounds__(256)
void fin_out(const float* __restrict__ part,
             const float* __restrict__ b_l,
             float* __restrict__ out)
{
    __shared__ float4 red4[256];
    const int q = threadIdx.x % 64;   // quad within 256-col block half
    const int c = threadIdx.x / 64;
    const int jq = blockIdx.x * 64 + q;
    const float4* p = reinterpret_cast<const float4*>(part);
    float4 acc = make_float4(0.f, 0.f, 0.f, 0.f);
    #pragma unroll
    for (int s = c; s < 256; s += 4) acc = f4add(acc, p[(size_t)s * 128 + jq]);
    red4[threadIdx.x] = acc;
    __syncthreads();
    if (threadIdx.x < 64) {
        float4 v = f4add(f4add(red4[q], red4[q + 64]),
                         f4add(red4[q + 128], red4[q + 192]));
        v = f4add(v, reinterpret_cast<const float4*>(b_l)[jq]);
        reinterpret_cast<float4*>(out)[jq] = v;
    }
}

extern "C" void kernel_launch(void* const* d_in, const int* in_sizes, int n_in,
                              void* d_out, int out_size)
{
    const float* x     = (const float*)d_in[0];
    const float* W1    = (const float*)d_in[1];
    const float* b1    = (const float*)d_in[2];
    const float* W2    = (const float*)d_in[3];
    const float* b2    = (const float*)d_in[4];
    const float* W_exp = (const float*)d_in[5];
    const float* b_exp = (const float*)d_in[6];
    const float* W_v   = (const float*)d_in[7];
    const float* b_v   = (const float*)d_in[8];
    const float* W_k   = (const float*)d_in[9];
    const float* b_k   = (const float*)d_in[10];
    const float* W_q   = (const float*)d_in[11];
    const float* b_q   = (const float*)d_in[12];
    const float* W_t   = (const float*)d_in[13];
    const float* b_t   = (const float*)d_in[14];
    const float* W_l   = (const float*)d_in[15];
    const float* b_l   = (const float*)d_in[16];
    const int*   tid   = (const int*)d_in[17];
    float* out = (float*)d_out;

    float *pA, *pB, *pC, *pD, *pE, *pF, *pG, *ekq;
    cudaGetSymbolAddress((void**)&pA, g_pA);
    cudaGetSymbolAddress((void**)&pB, g_pB);
    cudaGetSymbolAddress((void**)&pC, g_pC);
    cudaGetSymbolAddress((void**)&pD, g_pD);
    cudaGetSymbolAddress((void**)&pE, g_pE);
    cudaGetSymbolAddress((void**)&pF, g_pF);
    cudaGetSymbolAddress((void**)&pG, g_pG);
    cudaGetSymbolAddress((void**)&ekq, g_ekq);

    // A: pA = splitK(x @ W1)                  16MB, 256 blk
    gemv_k<256, 16, 2048, 1, 0, 0, 1, false, false, false>
        <<<dim3(2, 128, 1), 256>>>(W1, x, nullptr, nullptr, nullptr, pA);
    // B: h1 fused; pB = splitK(h1 @ W2)       16MB
    gemv_k<256, 16, 2048, 1, 1, 128, 2048, true, false, false>
        <<<dim3(2, 128, 1), 256>>>(W2, pA, b1, nullptr, nullptr, pB);
    // C: h2 fused; pC[n] = splitK(h2 @ W_exp[n])   256MB, 1024 blk
    gemv_k<256, 64, 2048, 1, 1, 128, 2048, true, false, false>
        <<<dim3(2, 32, 16), 256>>>(W_exp, pB, b2, nullptr, nullptr, pC);
    // D: e[n] fused; pD[n] = splitK(e[n] @ W_k[n])  32MB, 512 blk, GRP=4
    gemv_k<256, 64, 256, 4, 1, 32, 2048, true, false, true>
        <<<dim3(1, 32, 16), 256>>>(W_k, pC, b_exp, nullptr, nullptr, pD);
    // expkq
    fin_expkq<<<16, 256>>>(pD, b_k, W_q, b_q, tid, ekq);
    // E: e[n] fused; pE[n] = ekq[n] * splitK(e[n] @ W_v[n])   256MB
    gemv_k<256, 64, 2048, 1, 1, 32, 2048, true, true, true>
        <<<dim3(2, 32, 16), 256>>>(W_v, pC, b_exp, nullptr, ekq, pE);
    // F: res fused (512-slice flat reduce + ekq.b_v); pF = splitK(res @ W_t)  16MB
    gemv_k<256, 16, 2048, 1, 2, 512, 2048, false, false, false>
        <<<dim3(2, 128, 1), 256>>>(W_t, pE, nullptr, b_v, ekq, pF);
    // G: t fused; pG = splitK(t @ W_l)        4MB, 128 blk, GRP=2
    gemv_k<256, 16, 512, 2, 1, 128, 2048, true, false, false>
        <<<dim3(1, 128, 1), 256>>>(W_l, pF, b_t, nullptr, nullptr, pG);
    // out
    fin_out<<<2, 256>>>(pG, b_l, out);
}